// round 3
// baseline (speedup 1.0000x reference)
#include <cuda_runtime.h>
#include <cstdint>
#include <cstddef>

#define EXPERTS 8
#define TOK     2048
#define DMODEL  1024
#define HID     4096

// Intermediate hidden activations [E, T, H] fp32 (static scratch; no allocs allowed)
__device__ float g_hidden[(size_t)EXPERTS * TOK * HID];

// CTA tile 128x256, K-chunk 32, double-buffered
#define BM 128
#define BN 256
#define BK 32
#define APITCH 36     // floats: bank = (36*grp+qid)%32 = 4*grp+qid -> conflict-free
#define BPITCH 264    // floats: bank = (264*qid+grp)%32 = 8*qid+grp -> conflict-free
#define A_BYTES (BM * APITCH * 4)          // 18432
#define B_OFF   A_BYTES
#define STAGE_BYTES (A_BYTES + BK * BPITCH * 4)   // 18432 + 33792 = 52224
#define DSMEM_BYTES (2 * STAGE_BYTES)             // 104448

static __device__ __forceinline__ uint32_t smem_u32(const void* p) {
    uint32_t a;
    asm("{ .reg .u64 t; cvta.to.shared.u64 t, %1; cvt.u32.u64 %0, t; }" : "=r"(a) : "l"(p));
    return a;
}
static __device__ __forceinline__ void cp16(void* d, const void* s) {
    asm volatile("cp.async.cg.shared.global [%0], [%1], 16;" :: "r"(smem_u32(d)), "l"(s));
}
// Round 4 fp32 -> tf32 (rna) in place
static __device__ __forceinline__ void cvt16(float* p) {
    float4 v = *(const float4*)p;
    uint4 o;
    asm("cvt.rna.tf32.f32 %0, %1;" : "=r"(o.x) : "f"(v.x));
    asm("cvt.rna.tf32.f32 %0, %1;" : "=r"(o.y) : "f"(v.y));
    asm("cvt.rna.tf32.f32 %0, %1;" : "=r"(o.z) : "f"(v.z));
    asm("cvt.rna.tf32.f32 %0, %1;" : "=r"(o.w) : "f"(v.w));
    *(uint4*)p = o;
}

// C[M,N] = relu?(A[M,K]*B[K,N] + bias[N]); A,B,C row-major, batched over blockIdx.z.
// M%128==0, N%256==0, K%32==0.
template <bool RELU>
__global__ __launch_bounds__(256, 1)
void ffn_gemm(const float* __restrict__ A, const float* __restrict__ B,
              const float* __restrict__ bias, float* __restrict__ C,
              int M, int N, int K)
{
    extern __shared__ __align__(16) char smraw[];

    const int e = blockIdx.z;
    const float* Ae = A + (size_t)e * M * K;
    const float* Be = B + (size_t)e * K * N;
    const float* be = bias + (size_t)e * N;
    float*       Ce = C + (size_t)e * M * N;

    const int bm = blockIdx.y * BM;
    const int bn = blockIdx.x * BN;

    const int tid  = threadIdx.x;
    const int warp = tid >> 5;
    const int lane = tid & 31;
    const int wm   = (warp >> 2) * 64;   // 2 warp-rows
    const int wn   = (warp & 3) * 64;    // 4 warp-cols
    const int grp  = lane >> 2;          // 0..7
    const int qid  = lane & 3;           // 0..3

    float c[4][8][4];
    #pragma unroll
    for (int i = 0; i < 4; i++)
        #pragma unroll
        for (int j = 0; j < 8; j++)
            #pragma unroll
            for (int r = 0; r < 4; r++) c[i][j][r] = 0.f;

    const int nk = K / BK;

    // Per-thread fixed chunk ownership (same mapping for load & convert).
    // A: 128 rows x 8 chunks = 1024; B: 32 rows x 64 chunks = 2048. 4+8 per thread.
    auto issue = [&](int t, int s) {
        char* st = smraw + s * STAGE_BYTES;
        float* As = (float*)st;
        float* Bs = (float*)(st + B_OFF);
        const int k0 = t * BK;
        #pragma unroll
        for (int i = 0; i < 4; i++) {
            int f = tid + (i << 8);
            int r = f >> 3, cc = (f & 7) << 2;
            cp16(As + r * APITCH + cc, Ae + (size_t)(bm + r) * K + k0 + cc);
        }
        #pragma unroll
        for (int i = 0; i < 8; i++) {
            int f = tid + (i << 8);
            int r = f >> 6, cc = (f & 63) << 2;
            cp16(Bs + r * BPITCH + cc, Be + (size_t)(k0 + r) * N + bn + cc);
        }
        asm volatile("cp.async.commit_group;" ::: "memory");
    };
    auto convert = [&](int s) {
        char* st = smraw + s * STAGE_BYTES;
        float* As = (float*)st;
        float* Bs = (float*)(st + B_OFF);
        #pragma unroll
        for (int i = 0; i < 4; i++) {
            int f = tid + (i << 8);
            cvt16(As + (f >> 3) * APITCH + ((f & 7) << 2));
        }
        #pragma unroll
        for (int i = 0; i < 8; i++) {
            int f = tid + (i << 8);
            cvt16(Bs + (f >> 6) * BPITCH + ((f & 63) << 2));
        }
    };

    // Prologue: fill both buffers; convert buffer 0.
    issue(0, 0);
    issue(1, 1);
    asm volatile("cp.async.wait_group 1;" ::: "memory");
    convert(0);
    __syncthreads();

    for (int t = 0; t < nk; t++) {
        const int s = t & 1;
        const float* As = (const float*)(smraw + s * STAGE_BYTES);
        const float* Bs = (const float*)(smraw + s * STAGE_BYTES + B_OFF);

        #pragma unroll
        for (int kk = 0; kk < BK; kk += 8) {
            uint32_t a[4][4], b[8][2];
            #pragma unroll
            for (int i = 0; i < 4; i++) {
                const float* ap = As + (wm + i * 16 + grp) * APITCH + kk + qid;
                a[i][0] = __float_as_uint(ap[0]);
                a[i][1] = __float_as_uint(ap[8 * APITCH]);
                a[i][2] = __float_as_uint(ap[4]);
                a[i][3] = __float_as_uint(ap[8 * APITCH + 4]);
            }
            #pragma unroll
            for (int j = 0; j < 8; j++) {
                const float* bp = Bs + (kk + qid) * BPITCH + wn + j * 8 + grp;
                b[j][0] = __float_as_uint(bp[0]);
                b[j][1] = __float_as_uint(bp[4 * BPITCH]);
            }
            #pragma unroll
            for (int i = 0; i < 4; i++)
                #pragma unroll
                for (int j = 0; j < 8; j++) {
                    asm volatile(
                        "mma.sync.aligned.m16n8k8.row.col.f32.tf32.tf32.f32 "
                        "{%0,%1,%2,%3}, {%4,%5,%6,%7}, {%8,%9}, {%0,%1,%2,%3};"
                        : "+f"(c[i][j][0]), "+f"(c[i][j][1]),
                          "+f"(c[i][j][2]), "+f"(c[i][j][3])
                        : "r"(a[i][0]), "r"(a[i][1]), "r"(a[i][2]), "r"(a[i][3]),
                          "r"(b[j][0]), "r"(b[j][1]));
                }
        }

        __syncthreads();                       // all warps done reading buffer s
        if (t + 2 < nk) issue(t + 2, s);       // refill s
        if (t + 1 < nk) {
            if (t + 2 < nk) { asm volatile("cp.async.wait_group 1;" ::: "memory"); }
            else            { asm volatile("cp.async.wait_group 0;" ::: "memory"); }
            convert(s ^ 1);                    // own chunks only — no barrier needed
            __syncthreads();                   // publish converted buffer
        }
    }

    // Epilogue: bias + optional ReLU, float2 stores
    #pragma unroll
    for (int i = 0; i < 4; i++) {
        int r0 = bm + wm + i * 16 + grp;
        #pragma unroll
        for (int j = 0; j < 8; j++) {
            int cn = bn + wn + j * 8 + 2 * qid;
            float bv0 = be[cn], bv1 = be[cn + 1];
            float v0 = c[i][j][0] + bv0;
            float v1 = c[i][j][1] + bv1;
            float v2 = c[i][j][2] + bv0;
            float v3 = c[i][j][3] + bv1;
            if (RELU) {
                v0 = fmaxf(v0, 0.f); v1 = fmaxf(v1, 0.f);
                v2 = fmaxf(v2, 0.f); v3 = fmaxf(v3, 0.f);
            }
            *(float2*)&Ce[(size_t)r0 * N + cn]       = make_float2(v0, v1);
            *(float2*)&Ce[(size_t)(r0 + 8) * N + cn] = make_float2(v2, v3);
        }
    }
}

extern "C" void kernel_launch(void* const* d_in, const int* in_sizes, int n_in,
                              void* d_out, int out_size)
{
    const float* x  = (const float*)d_in[0];   // [E, T, D]
    const float* w1 = (const float*)d_in[1];   // [E, D, H]
    const float* b1 = (const float*)d_in[2];   // [E, 1, H]
    const float* w2 = (const float*)d_in[3];   // [E, H, D]
    const float* b2 = (const float*)d_in[4];   // [E, 1, D]
    float* out = (float*)d_out;                // [E, T, D]

    float* hid = nullptr;
    cudaGetSymbolAddress((void**)&hid, g_hidden);

    cudaFuncSetAttribute(ffn_gemm<true>,  cudaFuncAttributeMaxDynamicSharedMemorySize, DSMEM_BYTES);
    cudaFuncSetAttribute(ffn_gemm<false>, cudaFuncAttributeMaxDynamicSharedMemorySize, DSMEM_BYTES);

    dim3 blk(256);
    ffn_gemm<true><<<dim3(HID / BN, TOK / BM, EXPERTS), blk, DSMEM_BYTES>>>(
        x, w1, b1, hid, TOK, HID, DMODEL);
    ffn_gemm<false><<<dim3(DMODEL / BN, TOK / BM, EXPERTS), blk, DSMEM_BYTES>>>(
        hid, w2, b2, out, TOK, DMODEL, HID);
}

// round 4
// speedup vs baseline: 1.2679x; 1.2679x over previous
#include <cuda_runtime.h>
#include <cstdint>
#include <cstddef>

#define EXPERTS 8
#define TOK     2048
#define DMODEL  1024
#define HID     4096

// Intermediate hidden activations [E, T, H] fp32 (static scratch; no allocs allowed)
__device__ float g_hidden[(size_t)EXPERTS * TOK * HID];

// CTA tile 128x128, K-chunk 16, 3-stage smem pipeline, 2 CTAs/SM
#define BM 128
#define BN 128
#define BK 16
#define APITCH 20      // frag bank = (20*grp + qid)%32 -> all 32 distinct (verified R1)
#define BPITCH 136     // frag bank = (136*qid + grp)%32 = 8*qid+grp -> all 32 distinct
#define A_FLOATS (BM * APITCH)            // 2560
#define B_FLOATS (BK * BPITCH)            // 2176
#define S_FLOATS (A_FLOATS + B_FLOATS)    // 4736 (18944 B/stage)
#define DSMEM_BYTES (3 * S_FLOATS * 4)    // 56832 B

// fp32 -> tf32 round-to-nearest (bit pattern stays an fp32)
static __device__ __forceinline__ float4 cvt4(float4 v) {
    uint4 o;
    asm("cvt.rna.tf32.f32 %0, %1;" : "=r"(o.x) : "f"(v.x));
    asm("cvt.rna.tf32.f32 %0, %1;" : "=r"(o.y) : "f"(v.y));
    asm("cvt.rna.tf32.f32 %0, %1;" : "=r"(o.z) : "f"(v.z));
    asm("cvt.rna.tf32.f32 %0, %1;" : "=r"(o.w) : "f"(v.w));
    float4 r;
    r.x = __uint_as_float(o.x); r.y = __uint_as_float(o.y);
    r.z = __uint_as_float(o.z); r.w = __uint_as_float(o.w);
    return r;
}

// C[M,N] = relu?(A[M,K]*B[K,N] + bias[N]); row-major, batched over blockIdx.z.
// M%128==0, N%128==0, K%16==0.
template <bool RELU>
__global__ __launch_bounds__(256, 2)
void ffn_gemm(const float* __restrict__ A, const float* __restrict__ B,
              const float* __restrict__ bias, float* __restrict__ C,
              int M, int N, int K)
{
    extern __shared__ __align__(16) float sm[];

    const int e = blockIdx.z;
    const float* Ae = A + (size_t)e * M * K;
    const float* Be = B + (size_t)e * K * N;
    const float* be = bias + (size_t)e * N;
    float*       Ce = C + (size_t)e * M * N;

    const int bm = blockIdx.y * BM;
    const int bn = blockIdx.x * BN;

    const int tid  = threadIdx.x;
    const int warp = tid >> 5;
    const int lane = tid & 31;
    const int wm   = (warp >> 2) * 64;   // 2 warp-rows of 64
    const int wn   = (warp & 3) * 32;    // 4 warp-cols of 32
    const int grp  = lane >> 2;          // 0..7
    const int qid  = lane & 3;           // 0..3

    // Per-thread fixed chunks: A 2x float4, B 2x float4
    const int ar0 = tid >> 2,          ac0 = (tid & 3) << 2;
    const int ar1 = (tid + 256) >> 2,  ac1 = ac0;             // (tid+256)&3 == tid&3
    const int br0 = tid >> 5,          bc0 = (tid & 31) << 2;
    const int br1 = (tid + 256) >> 5,  bc1 = bc0;

    const float* gA0 = Ae + (size_t)(bm + ar0) * K + ac0;
    const float* gA1 = Ae + (size_t)(bm + ar1) * K + ac1;
    const float* gB0 = Be + (size_t)br0 * N + bn + bc0;
    const float* gB1 = Be + (size_t)br1 * N + bn + bc1;

    float c[4][4][4];
    #pragma unroll
    for (int i = 0; i < 4; i++)
        #pragma unroll
        for (int j = 0; j < 4; j++)
            #pragma unroll
            for (int r = 0; r < 4; r++) c[i][j][r] = 0.f;

    const int nk = K / BK;

    float4 ra0, ra1, rb0, rb1;           // 16 regs held between LDG and STS

    auto ldg = [&](int t) {
        const size_t k0 = (size_t)t * BK;
        ra0 = *(const float4*)(gA0 + k0);
        ra1 = *(const float4*)(gA1 + k0);
        rb0 = *(const float4*)(gB0 + k0 * N);
        rb1 = *(const float4*)(gB1 + k0 * N);
    };
    auto sts = [&](int s) {
        float* As = sm + s * S_FLOATS;
        float* Bs = As + A_FLOATS;
        *(float4*)(As + ar0 * APITCH + ac0) = cvt4(ra0);
        *(float4*)(As + ar1 * APITCH + ac1) = cvt4(ra1);
        *(float4*)(Bs + br0 * BPITCH + bc0) = cvt4(rb0);
        *(float4*)(Bs + br1 * BPITCH + bc1) = cvt4(rb1);
    };

    // Prologue: buf0 = tile0; regs hold tile1
    ldg(0);
    sts(0);
    if (nk > 1) ldg(1);
    __syncthreads();

    for (int t = 0; t < nk; t++) {
        const int s = t % 3;
        const float* As = sm + s * S_FLOATS;
        const float* Bs = As + A_FLOATS;

        #pragma unroll
        for (int kk = 0; kk < BK; kk += 8) {
            uint32_t a[4][4], b[4][2];
            #pragma unroll
            for (int i = 0; i < 4; i++) {
                const float* ap = As + (wm + i * 16 + grp) * APITCH + kk + qid;
                a[i][0] = __float_as_uint(ap[0]);
                a[i][1] = __float_as_uint(ap[8 * APITCH]);
                a[i][2] = __float_as_uint(ap[4]);
                a[i][3] = __float_as_uint(ap[8 * APITCH + 4]);
            }
            #pragma unroll
            for (int j = 0; j < 4; j++) {
                const float* bp = Bs + (kk + qid) * BPITCH + wn + j * 8 + grp;
                b[j][0] = __float_as_uint(bp[0]);
                b[j][1] = __float_as_uint(bp[4 * BPITCH]);
            }
            #pragma unroll
            for (int i = 0; i < 4; i++)
                #pragma unroll
                for (int j = 0; j < 4; j++) {
                    asm volatile(
                        "mma.sync.aligned.m16n8k8.row.col.f32.tf32.tf32.f32 "
                        "{%0,%1,%2,%3}, {%4,%5,%6,%7}, {%8,%9}, {%0,%1,%2,%3};"
                        : "+f"(c[i][j][0]), "+f"(c[i][j][1]),
                          "+f"(c[i][j][2]), "+f"(c[i][j][3])
                        : "r"(a[i][0]), "r"(a[i][1]), "r"(a[i][2]), "r"(a[i][3]),
                          "r"(b[j][0]), "r"(b[j][1]));
                }
        }

        // Publish tile t+1 into its (now free) stage, then prefetch t+2.
        if (t + 1 < nk) sts((t + 1) % 3);
        if (t + 2 < nk) ldg(t + 2);
        __syncthreads();
    }

    // Epilogue: bias + optional ReLU, float2 stores
    #pragma unroll
    for (int i = 0; i < 4; i++) {
        int r0 = bm + wm + i * 16 + grp;
        #pragma unroll
        for (int j = 0; j < 4; j++) {
            int cn = bn + wn + j * 8 + 2 * qid;
            float bv0 = be[cn], bv1 = be[cn + 1];
            float v0 = c[i][j][0] + bv0;
            float v1 = c[i][j][1] + bv1;
            float v2 = c[i][j][2] + bv0;
            float v3 = c[i][j][3] + bv1;
            if (RELU) {
                v0 = fmaxf(v0, 0.f); v1 = fmaxf(v1, 0.f);
                v2 = fmaxf(v2, 0.f); v3 = fmaxf(v3, 0.f);
            }
            *(float2*)&Ce[(size_t)r0 * N + cn]       = make_float2(v0, v1);
            *(float2*)&Ce[(size_t)(r0 + 8) * N + cn] = make_float2(v2, v3);
        }
    }
}

extern "C" void kernel_launch(void* const* d_in, const int* in_sizes, int n_in,
                              void* d_out, int out_size)
{
    const float* x  = (const float*)d_in[0];   // [E, T, D]
    const float* w1 = (const float*)d_in[1];   // [E, D, H]
    const float* b1 = (const float*)d_in[2];   // [E, 1, H]
    const float* w2 = (const float*)d_in[3];   // [E, H, D]
    const float* b2 = (const float*)d_in[4];   // [E, 1, D]
    float* out = (float*)d_out;                // [E, T, D]

    float* hid = nullptr;
    cudaGetSymbolAddress((void**)&hid, g_hidden);

    cudaFuncSetAttribute(ffn_gemm<true>,  cudaFuncAttributeMaxDynamicSharedMemorySize, DSMEM_BYTES);
    cudaFuncSetAttribute(ffn_gemm<false>, cudaFuncAttributeMaxDynamicSharedMemorySize, DSMEM_BYTES);

    dim3 blk(256);
    ffn_gemm<true><<<dim3(HID / BN, TOK / BM, EXPERTS), blk, DSMEM_BYTES>>>(
        x, w1, b1, hid, TOK, HID, DMODEL);
    ffn_gemm<false><<<dim3(DMODEL / BN, TOK / BM, EXPERTS), blk, DSMEM_BYTES>>>(
        hid, w2, b2, out, TOK, DMODEL, HID);
}

// round 5
// speedup vs baseline: 1.3568x; 1.0701x over previous
#include <cuda_runtime.h>
#include <cstdint>
#include <cstddef>

#define EXPERTS 8
#define TOK     2048
#define DMODEL  1024
#define HID     4096

// Intermediate hidden activations [E, T, H] fp32 (static scratch; no allocs allowed)
__device__ float g_hidden[(size_t)EXPERTS * TOK * HID];

// CTA tile 128x128, 128 threads (4 warps, 2x2, 64x64 each), BK=16, 3 stages, 2 CTAs/SM
#define BM 128
#define BN 128
#define BK 16
#define APITCH 20      // frag bank = (20*grp + qid)%32 -> all 32 distinct
#define BPITCH 136     // frag bank = (136*qid + grp + 8k)%32 = perm of 8*qid+grp -> distinct
#define A_FLOATS (BM * APITCH)            // 2560
#define B_FLOATS (BK * BPITCH)            // 2176
#define S_FLOATS (A_FLOATS + B_FLOATS)    // 4736 (18944 B/stage)
#define DSMEM_BYTES (3 * S_FLOATS * 4)    // 56832 B

// fp32 -> tf32 round-to-nearest (bit pattern stays an fp32)
static __device__ __forceinline__ float4 cvt4(float4 v) {
    uint4 o;
    asm("cvt.rna.tf32.f32 %0, %1;" : "=r"(o.x) : "f"(v.x));
    asm("cvt.rna.tf32.f32 %0, %1;" : "=r"(o.y) : "f"(v.y));
    asm("cvt.rna.tf32.f32 %0, %1;" : "=r"(o.z) : "f"(v.z));
    asm("cvt.rna.tf32.f32 %0, %1;" : "=r"(o.w) : "f"(v.w));
    float4 r;
    r.x = __uint_as_float(o.x); r.y = __uint_as_float(o.y);
    r.z = __uint_as_float(o.z); r.w = __uint_as_float(o.w);
    return r;
}

// C[M,N] = relu?(A[M,K]*B[K,N] + bias[N]); row-major, batched over blockIdx.z.
// M%128==0, N%128==0, K%16==0.
template <bool RELU>
__global__ __launch_bounds__(128, 2)
void ffn_gemm(const float* __restrict__ A, const float* __restrict__ B,
              const float* __restrict__ bias, float* __restrict__ C,
              int M, int N, int K)
{
    extern __shared__ __align__(16) float sm[];

    const int e = blockIdx.z;
    const float* Ae = A + (size_t)e * M * K;
    const float* Be = B + (size_t)e * K * N;
    const float* be = bias + (size_t)e * N;
    float*       Ce = C + (size_t)e * M * N;

    const int bm = blockIdx.y * BM;
    const int bn = blockIdx.x * BN;

    const int tid  = threadIdx.x;
    const int warp = tid >> 5;
    const int lane = tid & 31;
    const int wm   = (warp >> 1) * 64;   // 2 warp-rows of 64
    const int wn   = (warp & 1) * 64;    // 2 warp-cols of 64
    const int grp  = lane >> 2;          // 0..7
    const int qid  = lane & 3;           // 0..3

    // Per-thread fixed chunks: A 4x float4, B 4x float4 (128 threads)
    // A: f = tid + i*128 in [0,512): row f>>2, col4 (f&3)<<2
    // B: f = tid + i*128:            row f>>5, col4 (f&31)<<2
    const int arow = tid >> 2, acol = (tid & 3) << 2;
    const int brow = tid >> 5, bcol = (tid & 31) << 2;

    const float* gA[4];
    const float* gB[4];
    #pragma unroll
    for (int i = 0; i < 4; i++) {
        gA[i] = Ae + (size_t)(bm + arow + i * 32) * K + acol;
        gB[i] = Be + (size_t)(brow + i * 4) * N + bn + bcol;
    }

    float c[4][8][4];
    #pragma unroll
    for (int i = 0; i < 4; i++)
        #pragma unroll
        for (int j = 0; j < 8; j++)
            #pragma unroll
            for (int r = 0; r < 4; r++) c[i][j][r] = 0.f;

    const int nk = K / BK;

    float4 ra[4], rb[4];                  // 32 regs held between LDG and STS

    auto ldg = [&](int t) {
        const size_t k0 = (size_t)t * BK;
        #pragma unroll
        for (int i = 0; i < 4; i++) ra[i] = *(const float4*)(gA[i] + k0);
        #pragma unroll
        for (int i = 0; i < 4; i++) rb[i] = *(const float4*)(gB[i] + k0 * N);
    };
    auto sts = [&](int s) {
        float* As = sm + s * S_FLOATS;
        float* Bs = As + A_FLOATS;
        #pragma unroll
        for (int i = 0; i < 4; i++)
            *(float4*)(As + (arow + i * 32) * APITCH + acol) = cvt4(ra[i]);
        #pragma unroll
        for (int i = 0; i < 4; i++)
            *(float4*)(Bs + (brow + i * 4) * BPITCH + bcol) = cvt4(rb[i]);
    };

    // Prologue: buf0 = tile0; regs hold tile1
    ldg(0);
    sts(0);
    if (nk > 1) ldg(1);
    __syncthreads();

    for (int t = 0; t < nk; t++) {
        const int s = t % 3;
        const float* As = sm + s * S_FLOATS;
        const float* Bs = As + A_FLOATS;

        #pragma unroll
        for (int kk = 0; kk < BK; kk += 8) {
            uint32_t a[4][4], b[8][2];
            #pragma unroll
            for (int i = 0; i < 4; i++) {
                const float* ap = As + (wm + i * 16 + grp) * APITCH + kk + qid;
                a[i][0] = __float_as_uint(ap[0]);
                a[i][1] = __float_as_uint(ap[8 * APITCH]);
                a[i][2] = __float_as_uint(ap[4]);
                a[i][3] = __float_as_uint(ap[8 * APITCH + 4]);
            }
            #pragma unroll
            for (int j = 0; j < 8; j++) {
                const float* bp = Bs + (kk + qid) * BPITCH + wn + j * 8 + grp;
                b[j][0] = __float_as_uint(bp[0]);
                b[j][1] = __float_as_uint(bp[4 * BPITCH]);
            }
            #pragma unroll
            for (int i = 0; i < 4; i++)
                #pragma unroll
                for (int j = 0; j < 8; j++) {
                    asm volatile(
                        "mma.sync.aligned.m16n8k8.row.col.f32.tf32.tf32.f32 "
                        "{%0,%1,%2,%3}, {%4,%5,%6,%7}, {%8,%9}, {%0,%1,%2,%3};"
                        : "+f"(c[i][j][0]), "+f"(c[i][j][1]),
                          "+f"(c[i][j][2]), "+f"(c[i][j][3])
                        : "r"(a[i][0]), "r"(a[i][1]), "r"(a[i][2]), "r"(a[i][3]),
                          "r"(b[j][0]), "r"(b[j][1]));
                }
        }

        // Publish tile t+1 into its (now free) stage, then prefetch t+2.
        if (t + 1 < nk) sts((t + 1) % 3);
        if (t + 2 < nk) ldg(t + 2);
        __syncthreads();
    }

    // Epilogue: bias + optional ReLU, float2 stores
    #pragma unroll
    for (int i = 0; i < 4; i++) {
        int r0 = bm + wm + i * 16 + grp;
        #pragma unroll
        for (int j = 0; j < 8; j++) {
            int cn = bn + wn + j * 8 + 2 * qid;
            float bv0 = be[cn], bv1 = be[cn + 1];
            float v0 = c[i][j][0] + bv0;
            float v1 = c[i][j][1] + bv1;
            float v2 = c[i][j][2] + bv0;
            float v3 = c[i][j][3] + bv1;
            if (RELU) {
                v0 = fmaxf(v0, 0.f); v1 = fmaxf(v1, 0.f);
                v2 = fmaxf(v2, 0.f); v3 = fmaxf(v3, 0.f);
            }
            *(float2*)&Ce[(size_t)r0 * N + cn]       = make_float2(v0, v1);
            *(float2*)&Ce[(size_t)(r0 + 8) * N + cn] = make_float2(v2, v3);
        }
    }
}

extern "C" void kernel_launch(void* const* d_in, const int* in_sizes, int n_in,
                              void* d_out, int out_size)
{
    const float* x  = (const float*)d_in[0];   // [E, T, D]
    const float* w1 = (const float*)d_in[1];   // [E, D, H]
    const float* b1 = (const float*)d_in[2];   // [E, 1, H]
    const float* w2 = (const float*)d_in[3];   // [E, H, D]
    const float* b2 = (const float*)d_in[4];   // [E, 1, D]
    float* out = (float*)d_out;                // [E, T, D]

    float* hid = nullptr;
    cudaGetSymbolAddress((void**)&hid, g_hidden);

    cudaFuncSetAttribute(ffn_gemm<true>,  cudaFuncAttributeMaxDynamicSharedMemorySize, DSMEM_BYTES);
    cudaFuncSetAttribute(ffn_gemm<false>, cudaFuncAttributeMaxDynamicSharedMemorySize, DSMEM_BYTES);

    dim3 blk(128);
    ffn_gemm<true><<<dim3(HID / BN, TOK / BM, EXPERTS), blk, DSMEM_BYTES>>>(
        x, w1, b1, hid, TOK, HID, DMODEL);
    ffn_gemm<false><<<dim3(DMODEL / BN, TOK / BM, EXPERTS), blk, DSMEM_BYTES>>>(
        hid, w2, b2, out, TOK, DMODEL, HID);
}